// round 12
// baseline (speedup 1.0000x reference)
#include <cuda_runtime.h>
#include <math.h>

#define B_   64
#define C_   256
#define H_   56
#define W_   56
#define HW_  (H_*W_)          // 3136
#define NROWS (B_*C_)         // 16384
#define NV4   (HW_/4)         // 784 = 24*32 + 16
#define TOPK_ 38
#define HALF_ 2
#define NSEL  (B_*TOPK_)      // 2432

__device__ float    g_sum[NROWS];
__device__ int      g_amax[NROWS];
__device__ float    g_lam[NROWS];
__device__ unsigned g_box[NROWS];
__device__ int      g_sel[NSEL];

// ---------------- Kernel 1: warp-per-row sum + first-index argmax + copy ----------------
// One warp owns one row: no smem, no block barrier, pure shuffle reduction.
// x loads use DEFAULT caching so the tail of x stays L2-resident for the
// fixup kernel's re-read; output stores are evict-first (__stcs) so the
// write stream does not displace x from L2.
__global__ __launch_bounds__(256) void reduce_copy_kernel(const float* __restrict__ x,
                                                          float* __restrict__ out) {
    const int lane = threadIdx.x & 31;
    const int row  = (blockIdx.x * 256 + threadIdx.x) >> 5;   // grid 2048 * 8 warps = 16384

    const float4* __restrict__ xr  = (const float4*)(x   + (size_t)row * HW_);
    float4* __restrict__       orr = (float4*)(out + (size_t)row * HW_);

    float sum  = 0.0f;
    float best = -INFINITY;
    int   bidx = 0x7fffffff;

    // 24 full warp-strides of 32 float4, batched 4 at a time
    #pragma unroll
    for (int k = 0; k < 24; k += 4) {
        const int ia = (k + 0) * 32 + lane;
        const int ib = (k + 1) * 32 + lane;
        const int ic = (k + 2) * 32 + lane;
        const int id = (k + 3) * 32 + lane;
        float4 va = xr[ia];
        float4 vb = xr[ib];
        float4 vc = xr[ic];
        float4 vd = xr[id];
        __stcs(&orr[ia], va);
        __stcs(&orr[ib], vb);
        __stcs(&orr[ic], vc);
        __stcs(&orr[id], vd);

        sum += (va.x + va.y) + (va.z + va.w)
             + (vb.x + vb.y) + (vb.z + vb.w)
             + (vc.x + vc.y) + (vc.z + vc.w)
             + (vd.x + vd.y) + (vd.z + vd.w);

        // per-lane indices strictly increase across k, so ">" keeps first max
        int base = ia * 4;
        if (va.x > best) { best = va.x; bidx = base; }
        if (va.y > best) { best = va.y; bidx = base + 1; }
        if (va.z > best) { best = va.z; bidx = base + 2; }
        if (va.w > best) { best = va.w; bidx = base + 3; }
        base = ib * 4;
        if (vb.x > best) { best = vb.x; bidx = base; }
        if (vb.y > best) { best = vb.y; bidx = base + 1; }
        if (vb.z > best) { best = vb.z; bidx = base + 2; }
        if (vb.w > best) { best = vb.w; bidx = base + 3; }
        base = ic * 4;
        if (vc.x > best) { best = vc.x; bidx = base; }
        if (vc.y > best) { best = vc.y; bidx = base + 1; }
        if (vc.z > best) { best = vc.z; bidx = base + 2; }
        if (vc.w > best) { best = vc.w; bidx = base + 3; }
        base = id * 4;
        if (vd.x > best) { best = vd.x; bidx = base; }
        if (vd.y > best) { best = vd.y; bidx = base + 1; }
        if (vd.z > best) { best = vd.z; bidx = base + 2; }
        if (vd.w > best) { best = vd.w; bidx = base + 3; }
    }

    // tail: 16 float4 (lanes 0..15)
    if (lane < 16) {
        const int it = 768 + lane;
        float4 v = xr[it];
        __stcs(&orr[it], v);
        sum += (v.x + v.y) + (v.z + v.w);
        const int base = it * 4;
        if (v.x > best) { best = v.x; bidx = base; }
        if (v.y > best) { best = v.y; bidx = base + 1; }
        if (v.z > best) { best = v.z; bidx = base + 2; }
        if (v.w > best) { best = v.w; bidx = base + 3; }
    }

    // warp reduce (sum; argmax with min-index tie break)
    #pragma unroll
    for (int off = 16; off > 0; off >>= 1) {
        float osum  = __shfl_down_sync(0xffffffffu, sum,  off);
        float obest = __shfl_down_sync(0xffffffffu, best, off);
        int   obidx = __shfl_down_sync(0xffffffffu, bidx, off);
        sum += osum;
        if (obest > best || (obest == best && obidx < bidx)) { best = obest; bidx = obidx; }
    }

    if (lane == 0) { g_sum[row] = sum; g_amax[row] = bidx; }
}

// ---------------- Kernel 2: SE block + exact top-k + per-row params + compact list ----------------
__global__ __launch_bounds__(256) void se_topk_kernel(const float* __restrict__ w1,
                                                      const float* __restrict__ w2) {
    const int b = blockIdx.x;
    const int c = threadIdx.x;   // 256 threads, one per channel

    __shared__ float pooled[C_];
    __shared__ float hidden[16];
    __shared__ float M[C_];

    pooled[c] = g_sum[b * C_ + c] * (1.0f / (float)HW_);
    __syncthreads();

    if (c < 16) {
        float acc = 0.0f;
        #pragma unroll 8
        for (int j = 0; j < C_; j++) acc += pooled[j] * w1[c * C_ + j];
        hidden[c] = fmaxf(acc, 0.0f);
    }
    __syncthreads();

    float acc = 0.0f;
    #pragma unroll
    for (int d = 0; d < 16; d++) acc += hidden[d] * w2[c * 16 + d];
    const float m = 1.0f / (1.0f + expf(-acc));
    M[c] = m;
    __syncthreads();

    // exact rank with lax.top_k tie semantics (lower index wins);
    // ranks are a permutation of 0..255 -> unique compact slot for rank < TOPK_
    int rank = 0;
    #pragma unroll 8
    for (int j = 0; j < C_; j++) {
        float mj = M[j];
        rank += (mj > m) || (mj == m && j < c);
    }

    const int idx = b * C_ + c;
    const int amax = g_amax[idx];
    const int mh = amax / W_;
    const int mw = amax - mh * W_;
    const int h1  = max(mh - HALF_, 0);
    const int h2  = min(mh + HALF_, H_ - 1);
    const int wb1 = max(mw - HALF_, 0);
    const int wb2 = min(mw + HALF_, W_ - 1);
    const int area = (h2 - h1 + 1) * (wb2 - wb1 + 1);

    g_lam[idx] = (float)HW_ / (float)(HW_ - area);
    g_box[idx] = ((unsigned)h1 << 18) | ((unsigned)h2 << 12)
               | ((unsigned)wb1 << 6) | (unsigned)wb2;

    if (rank < TOPK_) g_sel[b * TOPK_ + rank] = idx;
}

// ---------------- Kernel 3: fixup the 2432 selected rows ----------------
// Reverse order: the tail of x was read most recently by kernel 1 (default
// caching there keeps it L2-resident), so these reads should largely hit L2.
__global__ __launch_bounds__(256) void fixup_kernel(const float* __restrict__ x,
                                                    float* __restrict__ out) {
    const int row = g_sel[(NSEL - 1) - blockIdx.x];
    const int tid = threadIdx.x;
    const unsigned box = g_box[row];
    const float lam = g_lam[row];
    const float4* __restrict__ xr  = (const float4*)(x   + (size_t)row * HW_);
    float4* __restrict__       orr = (float4*)(out + (size_t)row * HW_);

    const int h1  = (box >> 18) & 63;
    const int h2  = (box >> 12) & 63;
    const int wb1 = (box >> 6)  & 63;
    const int wb2 = box & 63;

    const int  i0 = tid, i1 = tid + 256, i2 = tid + 512, i3 = tid + 768;
    const bool p3 = (i3 < NV4);

    float4 v0 = xr[i0];
    float4 v1 = xr[i1];
    float4 v2 = xr[i2];
    float4 v3 = p3 ? xr[i3] : make_float4(0.f, 0.f, 0.f, 0.f);

    #pragma unroll
    for (int k = 0; k < 4; k++) {
        if (k == 3 && !p3) break;
        const int i = (k == 0) ? i0 : (k == 1) ? i1 : (k == 2) ? i2 : i3;
        float4 v   = (k == 0) ? v0 : (k == 1) ? v1 : (k == 2) ? v2 : v3;
        const int p = i * 4;        // W=56 divisible by 4 -> float4 never crosses rows
        const int h = p / W_;
        const int w = p - h * W_;
        float4 o;
        if (h >= h1 && h <= h2) {
            o.x = (w     >= wb1 && w     <= wb2) ? 0.0f : v.x * lam;
            o.y = (w + 1 >= wb1 && w + 1 <= wb2) ? 0.0f : v.y * lam;
            o.z = (w + 2 >= wb1 && w + 2 <= wb2) ? 0.0f : v.z * lam;
            o.w = (w + 3 >= wb1 && w + 3 <= wb2) ? 0.0f : v.w * lam;
        } else {
            o.x = v.x * lam; o.y = v.y * lam; o.z = v.z * lam; o.w = v.w * lam;
        }
        __stcs(&orr[i], o);
    }
}

extern "C" void kernel_launch(void* const* d_in, const int* in_sizes, int n_in,
                              void* d_out, int out_size) {
    const float* x  = (const float*)d_in[0];
    const float* w1 = (const float*)d_in[1];
    const float* w2 = (const float*)d_in[2];
    float* out = (float*)d_out;

    reduce_copy_kernel<<<NROWS / 8, 256>>>(x, out);
    se_topk_kernel<<<B_, 256>>>(w1, w2);
    fixup_kernel<<<NSEL, 256>>>(x, out);
}

// round 15
// speedup vs baseline: 1.0727x; 1.0727x over previous
#include <cuda_runtime.h>
#include <math.h>

#define B_   64
#define C_   256
#define H_   56
#define W_   56
#define HW_  (H_*W_)          // 3136
#define NROWS (B_*C_)         // 16384
#define NV4   (HW_/4)         // 784 = 24*32 + 16
#define TOPK_ 38
#define HALF_ 2
#define NSEL  (B_*TOPK_)      // 2432

__device__ float    g_sum[NROWS];
__device__ int      g_amax[NROWS];
__device__ float    g_lam[NROWS];
__device__ unsigned g_box[NROWS];
__device__ int      g_sel[NSEL];

// ---------------- Kernel 1: warp-per-row sum + first-index argmax + copy ----------------
// x loads evict-first (__ldcs): read-once stream, keep it out of L2.
// out stores DEFAULT (write-back): the tail of out stays L2-resident and the
// fixup kernel re-reads out (identical to x at that point) tail-first.
__global__ __launch_bounds__(256) void reduce_copy_kernel(const float* __restrict__ x,
                                                          float* __restrict__ out) {
    const int lane = threadIdx.x & 31;
    const int row  = (blockIdx.x * 256 + threadIdx.x) >> 5;   // grid 2048 * 8 warps = 16384

    const float4* __restrict__ xr  = (const float4*)(x   + (size_t)row * HW_);
    float4* __restrict__       orr = (float4*)(out + (size_t)row * HW_);

    float sum  = 0.0f;
    float best = -INFINITY;
    int   bidx = 0x7fffffff;

    // 24 full warp-strides of 32 float4, batched 4 at a time
    #pragma unroll
    for (int k = 0; k < 24; k += 4) {
        const int ia = (k + 0) * 32 + lane;
        const int ib = (k + 1) * 32 + lane;
        const int ic = (k + 2) * 32 + lane;
        const int id = (k + 3) * 32 + lane;
        float4 va = __ldcs(&xr[ia]);
        float4 vb = __ldcs(&xr[ib]);
        float4 vc = __ldcs(&xr[ic]);
        float4 vd = __ldcs(&xr[id]);
        orr[ia] = va;
        orr[ib] = vb;
        orr[ic] = vc;
        orr[id] = vd;

        sum += (va.x + va.y) + (va.z + va.w)
             + (vb.x + vb.y) + (vb.z + vb.w)
             + (vc.x + vc.y) + (vc.z + vc.w)
             + (vd.x + vd.y) + (vd.z + vd.w);

        // per-lane indices strictly increase across k, so ">" keeps first max
        int base = ia * 4;
        if (va.x > best) { best = va.x; bidx = base; }
        if (va.y > best) { best = va.y; bidx = base + 1; }
        if (va.z > best) { best = va.z; bidx = base + 2; }
        if (va.w > best) { best = va.w; bidx = base + 3; }
        base = ib * 4;
        if (vb.x > best) { best = vb.x; bidx = base; }
        if (vb.y > best) { best = vb.y; bidx = base + 1; }
        if (vb.z > best) { best = vb.z; bidx = base + 2; }
        if (vb.w > best) { best = vb.w; bidx = base + 3; }
        base = ic * 4;
        if (vc.x > best) { best = vc.x; bidx = base; }
        if (vc.y > best) { best = vc.y; bidx = base + 1; }
        if (vc.z > best) { best = vc.z; bidx = base + 2; }
        if (vc.w > best) { best = vc.w; bidx = base + 3; }
        base = id * 4;
        if (vd.x > best) { best = vd.x; bidx = base; }
        if (vd.y > best) { best = vd.y; bidx = base + 1; }
        if (vd.z > best) { best = vd.z; bidx = base + 2; }
        if (vd.w > best) { best = vd.w; bidx = base + 3; }
    }

    // tail: 16 float4 (lanes 0..15)
    if (lane < 16) {
        const int it = 768 + lane;
        float4 v = __ldcs(&xr[it]);
        orr[it] = v;
        sum += (v.x + v.y) + (v.z + v.w);
        const int base = it * 4;
        if (v.x > best) { best = v.x; bidx = base; }
        if (v.y > best) { best = v.y; bidx = base + 1; }
        if (v.z > best) { best = v.z; bidx = base + 2; }
        if (v.w > best) { best = v.w; bidx = base + 3; }
    }

    // warp reduce (sum; argmax with min-index tie break)
    #pragma unroll
    for (int off = 16; off > 0; off >>= 1) {
        float osum  = __shfl_down_sync(0xffffffffu, sum,  off);
        float obest = __shfl_down_sync(0xffffffffu, best, off);
        int   obidx = __shfl_down_sync(0xffffffffu, bidx, off);
        sum += osum;
        if (obest > best || (obest == best && obidx < bidx)) { best = obest; bidx = obidx; }
    }

    if (lane == 0) { g_sum[row] = sum; g_amax[row] = bidx; }
}

// ---------------- Kernel 2: SE block + exact top-k + per-row params + compact list ----------------
__global__ __launch_bounds__(256) void se_topk_kernel(const float* __restrict__ w1,
                                                      const float* __restrict__ w2) {
    const int b    = blockIdx.x;
    const int c    = threadIdx.x;   // 256 threads, one per channel
    const int lane = c & 31;
    const int wid  = c >> 5;        // 8 warps

    __shared__ float pooled[C_];
    __shared__ float hidden[16];
    __shared__ float M[C_];

    pooled[c] = g_sum[b * C_ + c] * (1.0f / (float)HW_);
    __syncthreads();

    // fc1: 16 outputs; each of 8 warps computes 2 outputs via warp-parallel dot
    #pragma unroll
    for (int t = 0; t < 2; t++) {
        const int d = wid + t * 8;
        float acc = 0.0f;
        #pragma unroll
        for (int j = lane; j < C_; j += 32) acc += pooled[j] * w1[d * C_ + j];
        #pragma unroll
        for (int off = 16; off > 0; off >>= 1)
            acc += __shfl_down_sync(0xffffffffu, acc, off);
        if (lane == 0) hidden[d] = fmaxf(acc, 0.0f);
    }
    __syncthreads();

    float acc = 0.0f;
    #pragma unroll
    for (int d = 0; d < 16; d++) acc += hidden[d] * w2[c * 16 + d];
    const float m = 1.0f / (1.0f + expf(-acc));
    M[c] = m;
    __syncthreads();

    // exact rank with lax.top_k tie semantics (lower index wins);
    // ranks are a permutation of 0..255 -> unique compact slot for rank < TOPK_
    int rank = 0;
    #pragma unroll 8
    for (int j = 0; j < C_; j++) {
        float mj = M[j];
        rank += (mj > m) || (mj == m && j < c);
    }

    const int idx = b * C_ + c;
    const int amax = g_amax[idx];
    const int mh = amax / W_;
    const int mw = amax - mh * W_;
    const int h1  = max(mh - HALF_, 0);
    const int h2  = min(mh + HALF_, H_ - 1);
    const int wb1 = max(mw - HALF_, 0);
    const int wb2 = min(mw + HALF_, W_ - 1);
    const int area = (h2 - h1 + 1) * (wb2 - wb1 + 1);

    g_lam[idx] = (float)HW_ / (float)(HW_ - area);
    g_box[idx] = ((unsigned)h1 << 18) | ((unsigned)h2 << 12)
               | ((unsigned)wb1 << 6) | (unsigned)wb2;

    if (rank < TOPK_) g_sel[b * TOPK_ + rank] = idx;
}

// ---------------- Kernel 3: fixup the 2432 selected rows (in place on out) ----------------
// Reads OUT (identical to x here): the tail of out was stored most recently by
// kernel 1 with default (resident) policy, so tail-first processing hits L2.
__global__ __launch_bounds__(256) void fixup_kernel(float* __restrict__ out) {
    const int row = g_sel[(NSEL - 1) - blockIdx.x];
    const int tid = threadIdx.x;
    const unsigned box = g_box[row];
    const float lam = g_lam[row];
    float4* __restrict__ orr = (float4*)(out + (size_t)row * HW_);

    const int h1  = (box >> 18) & 63;
    const int h2  = (box >> 12) & 63;
    const int wb1 = (box >> 6)  & 63;
    const int wb2 = box & 63;

    const int  i0 = tid, i1 = tid + 256, i2 = tid + 512, i3 = tid + 768;
    const bool p3 = (i3 < NV4);

    float4 v0 = orr[i0];
    float4 v1 = orr[i1];
    float4 v2 = orr[i2];
    float4 v3 = p3 ? orr[i3] : make_float4(0.f, 0.f, 0.f, 0.f);

    #pragma unroll
    for (int k = 0; k < 4; k++) {
        if (k == 3 && !p3) break;
        const int i = (k == 0) ? i0 : (k == 1) ? i1 : (k == 2) ? i2 : i3;
        float4 v   = (k == 0) ? v0 : (k == 1) ? v1 : (k == 2) ? v2 : v3;
        const int p = i * 4;        // W=56 divisible by 4 -> float4 never crosses rows
        const int h = p / W_;
        const int w = p - h * W_;
        float4 o;
        if (h >= h1 && h <= h2) {
            o.x = (w     >= wb1 && w     <= wb2) ? 0.0f : v.x * lam;
            o.y = (w + 1 >= wb1 && w + 1 <= wb2) ? 0.0f : v.y * lam;
            o.z = (w + 2 >= wb1 && w + 2 <= wb2) ? 0.0f : v.z * lam;
            o.w = (w + 3 >= wb1 && w + 3 <= wb2) ? 0.0f : v.w * lam;
        } else {
            o.x = v.x * lam; o.y = v.y * lam; o.z = v.z * lam; o.w = v.w * lam;
        }
        orr[i] = o;
    }
}

extern "C" void kernel_launch(void* const* d_in, const int* in_sizes, int n_in,
                              void* d_out, int out_size) {
    const float* x  = (const float*)d_in[0];
    const float* w1 = (const float*)d_in[1];
    const float* w2 = (const float*)d_in[2];
    float* out = (float*)d_out;

    reduce_copy_kernel<<<NROWS / 8, 256>>>(x, out);
    se_topk_kernel<<<B_, 256>>>(w1, w2);
    fixup_kernel<<<NSEL, 256>>>(out);
}